// round 4
// baseline (speedup 1.0000x reference)
#include <cuda_runtime.h>
#include <math.h>

// Shape (fixed by the dataset)
#define NB 8
#define NT 4096
#define NH 8
#define ND 64
#define DQ 16                 // float4 lanes over D
#define L 4                   // timesteps per thread
#define SUBS 32               // sub-chunks per tile (block = SUBS*DQ = 512 threads)
#define TILE_T (L * SUBS)     // 128 timesteps per tile
#define NTILES (NT / TILE_T)  // 32
#define NBH (NB * NH)         // 64
#define F4T (NH * ND / 4)     // float4 stride between consecutive t = 128

// Decoupled-lookback state (per tile, per channel)
__device__ float4 g_S[NTILES * NBH * DQ];   // tile aggregate
__device__ float4 g_Y[NTILES * NBH * DQ];   // tile inclusive end value
__device__ int    g_flag[NTILES * NBH];     // 0 = empty, 1 = A, 2 = P

static __device__ __forceinline__ void st_release(int* p, int v) {
    asm volatile("st.release.gpu.s32 [%0], %1;" :: "l"(p), "r"(v) : "memory");
}
static __device__ __forceinline__ int ld_acquire(const int* p) {
    int v;
    asm volatile("ld.acquire.gpu.s32 %0, [%1];" : "=r"(v) : "l"(p) : "memory");
    return v;
}

__global__ void k_zero() { g_flag[blockIdx.x * 1024 + threadIdx.x] = 0; }

__global__ __launch_bounds__(512, 3) void k_scan(
    const float4* __restrict__ v, const float4* __restrict__ x,
    const float4* __restrict__ v0, const float* __restrict__ sw,
    float4* __restrict__ out)
{
    __shared__ float4 sm[SUBS * DQ];     // aggregates -> exclusive prefixes (in place)
    __shared__ float4 carry_sm[DQ];

    const int tid  = threadIdx.x;
    const int dq   = tid & 15;
    const int sub  = tid >> 4;
    const int tile = blockIdx.x;
    const int bh   = blockIdx.y;
    const int h    = bh & (NH - 1);
    const int b    = bh >> 3;

    const float a  = 1.0f / (1.0f + expf(-sw[h]));
    const float om = 1.0f - a;
    const float cf = a * (om / fmaxf(om, 1e-6f));
    float aL = a;                                    // a^L = a^4
    #pragma unroll
    for (int i = 0; i < 2; ++i) aL *= aL;
    float aT = aL;                                   // a^TILE_T = a^128
    #pragma unroll
    for (int i = 0; i < 5; ++i) aT *= aT;

    const int t0   = tile * TILE_T + sub * L;
    const int base = ((b * NT + t0) * NH + h) * (ND / 4) + dq;

    // ---- local scan of L steps, zero-seeded, kept in registers ----
    float4 vv[L], xx[L];
    #pragma unroll
    for (int i = 0; i < L; ++i) {                    // all loads issued up front
        vv[i] = __ldcs(&v[base + i * F4T]);
        xx[i] = __ldcs(&x[base + i * F4T]);
    }
    float4 y[L];
    float4 yy = make_float4(0.f, 0.f, 0.f, 0.f);
    #pragma unroll
    for (int i = 0; i < L; ++i) {
        yy.x = fmaf(a, yy.x, fmaf(om, vv[i].x, cf * xx[i].x));
        yy.y = fmaf(a, yy.y, fmaf(om, vv[i].y, cf * xx[i].y));
        yy.z = fmaf(a, yy.z, fmaf(om, vv[i].z, cf * xx[i].z));
        yy.w = fmaf(a, yy.w, fmaf(om, vv[i].w, cf * xx[i].w));
        y[i] = yy;
    }
    sm[sub * DQ + dq] = yy;              // sub-chunk aggregate
    __syncthreads();

    // ---- in-block scan across sub-chunks + lookback (first 16 threads) ----
    if (tid < DQ) {
        float4 I = make_float4(0.f, 0.f, 0.f, 0.f);
        #pragma unroll
        for (int k = 0; k < SUBS; ++k) {
            float4 t4 = sm[k * DQ + tid];
            sm[k * DQ + tid] = I;        // exclusive prefix
            I.x = fmaf(aL, I.x, t4.x);
            I.y = fmaf(aL, I.y, t4.y);
            I.z = fmaf(aL, I.z, t4.z);
            I.w = fmaf(aL, I.w, t4.w);
        }
        const float4 blockagg = I;
        const int sidx = (tile * NBH + bh) * DQ + tid;
        const int fidx = tile * NBH + bh;

        if (tile > 0) {                  // publish aggregate ASAP
            __stcg(&g_S[sidx], blockagg);
            __syncwarp(0x0000FFFFu);
            if (tid == 0) st_release(&g_flag[fidx], 1);
        }

        // lookback for the tile-entry carry
        float4 carry;
        if (tile == 0) {
            carry = __ldg(&v0[h * DQ + tid]);
        } else {
            float4 acc = make_float4(0.f, 0.f, 0.f, 0.f);
            float  d   = 1.0f;
            int    j   = tile - 1;
            for (;;) {
                int f = 0;
                if (tid == 0) {
                    do { f = ld_acquire(&g_flag[j * NBH + bh]); } while (f == 0);
                }
                f = __shfl_sync(0x0000FFFFu, f, 0);
                const int pidx = (j * NBH + bh) * DQ + tid;
                if (f == 2) {
                    float4 Y = __ldcg(&g_Y[pidx]);
                    carry.x = fmaf(d, Y.x, acc.x);
                    carry.y = fmaf(d, Y.y, acc.y);
                    carry.z = fmaf(d, Y.z, acc.z);
                    carry.w = fmaf(d, Y.w, acc.w);
                    break;
                } else {
                    float4 S = __ldcg(&g_S[pidx]);
                    acc.x = fmaf(d, S.x, acc.x);
                    acc.y = fmaf(d, S.y, acc.y);
                    acc.z = fmaf(d, S.z, acc.z);
                    acc.w = fmaf(d, S.w, acc.w);
                    d *= aT;
                    --j;
                }
            }
        }

        // publish inclusive end value
        float4 ye;
        ye.x = fmaf(aT, carry.x, blockagg.x);
        ye.y = fmaf(aT, carry.y, blockagg.y);
        ye.z = fmaf(aT, carry.z, blockagg.z);
        ye.w = fmaf(aT, carry.w, blockagg.w);
        __stcg(&g_Y[sidx], ye);
        __syncwarp(0x0000FFFFu);
        if (tid == 0) st_release(&g_flag[fidx], 2);

        carry_sm[tid] = carry;
    }
    __syncthreads();

    // ---- apply carry in registers and write output (single store pass) ----
    const float4 carry = carry_sm[dq];
    // p = a^(L*sub) via exp2: rel err ~1e-7, well inside tolerance
    const float p = exp2f((float)(L * sub) * log2f(a));
    const float4 E = sm[sub * DQ + dq];   // within-block exclusive prefix
    float4 c;
    c.x = fmaf(p, carry.x, E.x);
    c.y = fmaf(p, carry.y, E.y);
    c.z = fmaf(p, carry.z, E.z);
    c.w = fmaf(p, carry.w, E.w);

    float pa = a;
    #pragma unroll
    for (int i = 0; i < L; ++i) {
        float4 o;
        o.x = fmaf(pa, c.x, y[i].x);
        o.y = fmaf(pa, c.y, y[i].y);
        o.z = fmaf(pa, c.z, y[i].z);
        o.w = fmaf(pa, c.w, y[i].w);
        __stcs(&out[base + i * F4T], o);
        pa *= a;
    }
}

extern "C" void kernel_launch(void* const* d_in, const int* in_sizes, int n_in,
                              void* d_out, int out_size)
{
    const float4* v  = (const float4*)d_in[0];   // values   [B,T,H,D] f32
    const float4* x  = (const float4*)d_in[1];   // aux      [B,T,H,D] f32
    const float4* v0 = (const float4*)d_in[2];   // v0       [1,1,H,D] f32
    const float*  sw = (const float*)d_in[3];    // weight   [H,1]     f32

    k_zero<<<(NTILES * NBH) / 1024, 1024>>>();
    k_scan<<<dim3(NTILES, NBH), SUBS * DQ>>>(v, x, (const float4*)v0, sw, (float4*)d_out);
}

// round 7
// speedup vs baseline: 1.1449x; 1.1449x over previous
#include <cuda_runtime.h>
#include <math.h>

// Shape (fixed by the dataset)
#define NB 8
#define NT 4096
#define NH 8
#define ND 64
#define DQ 16                 // float4 lanes over D
#define L 8                   // timesteps per thread
#define SUBS 32               // sub-chunks per tile (block = SUBS*DQ = 512 threads)
#define TILE_T (L * SUBS)     // 256 timesteps per tile
#define NTILES (NT / TILE_T)  // 16
#define NBH (NB * NH)         // 64
#define F4T (NH * ND / 4)     // float4 stride between consecutive t = 128
#define SMP 17                // padded smem stride (float4 units)

// Decoupled-lookback state, per (tile, channel, dq-warp)
__device__ float4 g_S[NTILES * NBH * DQ];   // tile aggregate
__device__ float4 g_Y[NTILES * NBH * DQ];   // tile inclusive end value
__device__ int    g_flag[NTILES * NBH * DQ];// 0 = empty, 1 = A, 2 = P

static __device__ __forceinline__ void st_release(int* p, int v) {
    asm volatile("st.release.gpu.s32 [%0], %1;" :: "l"(p), "r"(v) : "memory");
}
static __device__ __forceinline__ int ld_acquire(const int* p) {
    int v;
    asm volatile("ld.acquire.gpu.s32 %0, [%1];" : "=r"(v) : "l"(p) : "memory");
    return v;
}
static __device__ __forceinline__ float4 fma4(float s, float4 A, float4 B) {
    return make_float4(fmaf(s, A.x, B.x), fmaf(s, A.y, B.y),
                       fmaf(s, A.z, B.z), fmaf(s, A.w, B.w));
}

__global__ void k_zero() { g_flag[blockIdx.x * 1024 + threadIdx.x] = 0; }  // grid = 16

__global__ __launch_bounds__(512, 2) void k_scan(
    const float4* __restrict__ v, const float4* __restrict__ x,
    const float4* __restrict__ v0, const float* __restrict__ sw,
    float4* __restrict__ out)
{
    __shared__ float4 smT[SUBS * SMP];   // aggregates -> exclusive prefixes (padded)
    __shared__ float4 carry_sm[DQ];

    const int tid  = threadIdx.x;
    const int dq   = tid & 15;
    const int sub  = tid >> 4;
    const int wid  = tid >> 5;          // warp id == dq handled in phase B
    const int lane = tid & 31;
    const int tile = blockIdx.x;
    const int bh   = blockIdx.y;
    const int h    = bh & (NH - 1);
    const int b    = bh >> 3;

    const float a  = 1.0f / (1.0f + expf(-sw[h]));
    const float om = 1.0f - a;
    const float cf = a * (om / fmaxf(om, 1e-6f));
    // a^8 and its powers of two up to a^128; aT = a^256
    float a8_1 = a;
    #pragma unroll
    for (int i = 0; i < 3; ++i) a8_1 *= a8_1;          // a^8
    const float a8_2  = a8_1 * a8_1;                   // a^16
    const float a8_4  = a8_2 * a8_2;                   // a^32
    const float a8_8  = a8_4 * a8_4;                   // a^64
    const float a8_16 = a8_8 * a8_8;                   // a^128
    const float aT    = a8_16 * a8_16;                 // a^256 = a^TILE_T

    const int base = ((b * NT + tile * TILE_T + sub * L) * NH + h) * (ND / 4) + dq;

    // ---- phase A: local scan of L steps (zero-seeded) in registers ----
    float4 y[L];
    float4 yy = make_float4(0.f, 0.f, 0.f, 0.f);
    #pragma unroll
    for (int i = 0; i < L; ++i) {
        float4 vv = v[base + i * F4T];
        float4 xx = x[base + i * F4T];
        yy.x = fmaf(a, yy.x, fmaf(om, vv.x, cf * xx.x));
        yy.y = fmaf(a, yy.y, fmaf(om, vv.y, cf * xx.y));
        yy.z = fmaf(a, yy.z, fmaf(om, vv.z, cf * xx.z));
        yy.w = fmaf(a, yy.w, fmaf(om, vv.w, cf * xx.w));
        y[i] = yy;
    }
    smT[sub * SMP + dq] = yy;            // sub-chunk aggregate (transposed access later)
    __syncthreads();

    // ---- phase B: warp wid scans the 32 sub-aggregates of dq == wid ----
    // Weighted Kogge-Stone inclusive scan: I_s = sum_{k<=s} a8^(s-k) S_k
    float4 I = smT[lane * SMP + wid];
    {
        float f = a8_1;
        #pragma unroll
        for (int o = 1; o < 32; o <<= 1) {
            float4 t;
            t.x = __shfl_up_sync(0xFFFFFFFFu, I.x, o);
            t.y = __shfl_up_sync(0xFFFFFFFFu, I.y, o);
            t.z = __shfl_up_sync(0xFFFFFFFFu, I.z, o);
            t.w = __shfl_up_sync(0xFFFFFFFFu, I.w, o);
            if (lane >= o) I = fma4(f, t, I);
            f *= f;
        }
    }
    const float4 blockagg = I;           // valid at lane 31
    // exclusive prefix: entry state of sub-chunk s (zero tile seed) = I_{s-1}
    // (the decay through the sub-chunk's own steps is applied via pa in phase D)
    float4 E;
    E.x = __shfl_up_sync(0xFFFFFFFFu, I.x, 1);
    E.y = __shfl_up_sync(0xFFFFFFFFu, I.y, 1);
    E.z = __shfl_up_sync(0xFFFFFFFFu, I.z, 1);
    E.w = __shfl_up_sync(0xFFFFFFFFu, I.w, 1);
    if (lane == 0) E = make_float4(0.f, 0.f, 0.f, 0.f);

    const int fbase = (tile * NBH + bh) * DQ + wid;

    // publish aggregate A as early as possible (per-warp, self-ordered release)
    if (tile > 0 && lane == 31) {
        __stcg(&g_S[fbase], blockagg);
        st_release(&g_flag[fbase], 1);
    }
    smT[lane * SMP + wid] = E;           // write exclusive prefixes back

    // ---- phase C: single-round parallel lookback (per warp) ----
    float4 carry;
    if (tile == 0) {
        carry = __ldg(&v0[h * DQ + wid]);
    } else {
        // per-lane decay aT^lane from bits (exact products)
        const float aT2 = aT * aT, aT4 = aT2 * aT2, aT8 = aT4 * aT4;
        float dj = 1.0f;
        if (lane & 1) dj *= aT;
        if (lane & 2) dj *= aT2;
        if (lane & 4) dj *= aT4;
        if (lane & 8) dj *= aT8;
        const int pred  = tile - 1 - lane;            // valid when lane < tile
        const int pidx  = (pred * NBH + bh) * DQ + wid;
        int jstar;
        for (;;) {
            int fl = 0;
            if (lane < tile) fl = ld_acquire(&g_flag[pidx]);
            unsigned bp = __ballot_sync(0xFFFFFFFFu, fl == 2);
            unsigned bo = __ballot_sync(0xFFFFFFFFu, fl != 0);
            if (bp) {
                jstar = __ffs(bp) - 1;                // nearest P
                if (((~bo) & ((1u << jstar) - 1u)) == 0) break;   // all closer have >= A
            }
            __nanosleep(64);
        }
        // carry = sum_{j<jstar} aT^j S[tile-1-j]  +  aT^jstar Y[tile-1-jstar]
        float4 val = make_float4(0.f, 0.f, 0.f, 0.f);
        if (lane < jstar)       val = fma4(dj, __ldcg(&g_S[pidx]), val);
        else if (lane == jstar) val = fma4(dj, __ldcg(&g_Y[pidx]), val);
        #pragma unroll
        for (int o = 16; o >= 1; o >>= 1) {
            val.x += __shfl_xor_sync(0xFFFFFFFFu, val.x, o);
            val.y += __shfl_xor_sync(0xFFFFFFFFu, val.y, o);
            val.z += __shfl_xor_sync(0xFFFFFFFFu, val.z, o);
            val.w += __shfl_xor_sync(0xFFFFFFFFu, val.w, o);
        }
        carry = val;
    }

    // publish inclusive end value P (per-warp, self-ordered release)
    if (lane == 31) {
        float4 ye = fma4(aT, carry, blockagg);
        __stcg(&g_Y[fbase], ye);
        st_release(&g_flag[fbase], 2);
    }
    if (lane == 0) carry_sm[wid] = carry;
    __syncthreads();

    // ---- phase D: apply carry in registers, single store pass ----
    const float4 carry2 = carry_sm[dq];
    const float4 E2 = smT[sub * SMP + dq];
    // p = a8^sub from bits (exact products)
    float p = 1.0f;
    if (sub & 1)  p *= a8_1;
    if (sub & 2)  p *= a8_2;
    if (sub & 4)  p *= a8_4;
    if (sub & 8)  p *= a8_8;
    if (sub & 16) p *= a8_16;
    const float4 c = fma4(p, carry2, E2);

    float pa = a;
    #pragma unroll
    for (int i = 0; i < L; ++i) {
        out[base + i * F4T] = fma4(pa, c, y[i]);
        pa *= a;
    }
}

extern "C" void kernel_launch(void* const* d_in, const int* in_sizes, int n_in,
                              void* d_out, int out_size)
{
    const float4* v  = (const float4*)d_in[0];   // values   [B,T,H,D] f32
    const float4* x  = (const float4*)d_in[1];   // aux      [B,T,H,D] f32
    const float4* v0 = (const float4*)d_in[2];   // v0       [1,1,H,D] f32
    const float*  sw = (const float*)d_in[3];    // weight   [H,1]     f32

    k_zero<<<(NTILES * NBH * DQ) / 1024, 1024>>>();
    k_scan<<<dim3(NTILES, NBH), SUBS * DQ>>>(v, x, (const float4*)v0, sw, (float4*)d_out);
}